// round 1
// baseline (speedup 1.0000x reference)
#include <cuda_runtime.h>
#include <cuda_bf16.h>
#include <cstddef>

// Problem constants
#define BATCH 8
#define SEQ   512
#define NTOK  4096      // BATCH*SEQ
#define EMB   1024
#define E3    3072
#define NHEAD 16
#define HDIM  64
#define HID   4096
#define ODIM  128
#define NLAYER 8

// ---------------------------------------------------------------------------
// Scratch (device globals; allocation is forbidden)
// ---------------------------------------------------------------------------
__device__ float g_z   [(size_t)NTOK * EMB];   // 16 MB
__device__ float g_qkv [(size_t)NTOK * E3];    // 48 MB
__device__ float g_attn[(size_t)NTOK * EMB];   // 16 MB
__device__ float g_tmp [(size_t)NTOK * EMB];   // 16 MB
__device__ float g_hid [(size_t)NTOK * HID];   // 64 MB
__device__ float g_M   [ODIM * ODIM];
__device__ float g_aug [ODIM * 2 * ODIM];
__device__ float g_P   [ODIM * EMB];

// ---------------------------------------------------------------------------
// Generic NT GEMM: C[M,N] = A[M,K] * B[N,K]^T  (+bias)(+relu)
// M,N multiples of 128; K multiple of 32.
// ---------------------------------------------------------------------------
#define BM 128
#define BN 128
#define BK 32

__global__ void __launch_bounds__(256) gemm_nt_kernel(
    const float* __restrict__ A, const float* __restrict__ B,
    const float* __restrict__ bias, float* __restrict__ C,
    int M, int N, int K, int op)   // op: 0=none, 1=bias, 2=bias+relu
{
    __shared__ float As[BK][BM + 4];
    __shared__ float Bs[BK][BN + 4];

    const int bm = blockIdx.y * BM;
    const int bn = blockIdx.x * BN;
    const int tid = threadIdx.x;
    const int tm = (tid >> 4) << 3;   // (tid/16)*8
    const int tn = (tid & 15) << 3;   // (tid%16)*8

    float acc[8][8];
#pragma unroll
    for (int i = 0; i < 8; i++)
#pragma unroll
        for (int j = 0; j < 8; j++) acc[i][j] = 0.f;

    for (int k0 = 0; k0 < K; k0 += BK) {
#pragma unroll
        for (int i = 0; i < 4; i++) {
            int idx = tid + i * 256;            // 0..1023
            int row = idx >> 3;                 // 0..127
            int col = (idx & 7) << 2;           // 0,4,...,28
            float4 a = *(const float4*)(A + (size_t)(bm + row) * K + k0 + col);
            As[col + 0][row] = a.x; As[col + 1][row] = a.y;
            As[col + 2][row] = a.z; As[col + 3][row] = a.w;
            float4 b = *(const float4*)(B + (size_t)(bn + row) * K + k0 + col);
            Bs[col + 0][row] = b.x; Bs[col + 1][row] = b.y;
            Bs[col + 2][row] = b.z; Bs[col + 3][row] = b.w;
        }
        __syncthreads();
#pragma unroll
        for (int kk = 0; kk < BK; kk++) {
            float4 a0 = *(const float4*)&As[kk][tm];
            float4 a1 = *(const float4*)&As[kk][tm + 4];
            float4 b0 = *(const float4*)&Bs[kk][tn];
            float4 b1 = *(const float4*)&Bs[kk][tn + 4];
            float av[8] = {a0.x, a0.y, a0.z, a0.w, a1.x, a1.y, a1.z, a1.w};
            float bv[8] = {b0.x, b0.y, b0.z, b0.w, b1.x, b1.y, b1.z, b1.w};
#pragma unroll
            for (int i = 0; i < 8; i++)
#pragma unroll
                for (int j = 0; j < 8; j++)
                    acc[i][j] += av[i] * bv[j];
        }
        __syncthreads();
    }

#pragma unroll
    for (int i = 0; i < 8; i++) {
        size_t m = bm + tm + i;
#pragma unroll
        for (int j = 0; j < 8; j++) {
            int n = bn + tn + j;
            float v = acc[i][j];
            if (op >= 1) v += bias[n];
            if (op == 2) v = fmaxf(v, 0.f);
            C[m * N + n] = v;
        }
    }
}

// ---------------------------------------------------------------------------
// Gauss-Jordan inverse of the SPD 128x128 matrix g_M -> right half of g_aug
// Single block, 256 threads.
// ---------------------------------------------------------------------------
__global__ void __launch_bounds__(256) gj_kernel()
{
    const int tid = threadIdx.x;
    for (int idx = tid; idx < ODIM * 2 * ODIM; idx += 256) {
        int r = idx >> 8, c = idx & 255;
        g_aug[idx] = (c < ODIM) ? g_M[r * ODIM + c] : ((c - ODIM) == r ? 1.f : 0.f);
    }
    __syncthreads();

    const int r = tid >> 1;
    const int cb = (tid & 1) << 7;   // 0 or 128
    for (int k = 0; k < ODIM; k++) {
        float ip = 1.f / g_aug[k * 256 + k];
        __syncthreads();
        g_aug[k * 256 + tid] *= ip;        // each thread normalizes one column of row k
        __syncthreads();
        float f = (r != k) ? g_aug[r * 256 + k] : 0.f;
        __syncthreads();
        const float* prow = &g_aug[k * 256 + cb];
        float* rrow = &g_aug[r * 256 + cb];
#pragma unroll 8
        for (int c = 0; c < 128; c++) rrow[c] -= f * prow[c];
        __syncthreads();
    }
}

// P[o][e] = sum_j Minv[o][j] * W_obs[j][e].  grid(EMB/256, ODIM), 256 threads.
__global__ void __launch_bounds__(256) pmat_kernel(const float* __restrict__ W)
{
    const int o = blockIdx.y;
    const int e = blockIdx.x * 256 + threadIdx.x;
    __shared__ float sm[ODIM];
    if (threadIdx.x < ODIM) sm[threadIdx.x] = g_aug[o * 256 + ODIM + threadIdx.x];
    __syncthreads();
    float acc = 0.f;
#pragma unroll 8
    for (int j = 0; j < ODIM; j++) acc += sm[j] * W[(size_t)j * EMB + e];
    g_P[(size_t)o * EMB + e] = acc;
}

// z[t][e] = sum_o x[t][o] * P[o][e]  + PE(s,e).  grid(NTOK), 256 threads.
__global__ void __launch_bounds__(256) embed_kernel(const float* __restrict__ x)
{
    const int t = blockIdx.x;
    const int s = t & (SEQ - 1);
    __shared__ float sx[ODIM];
    if (threadIdx.x < ODIM) sx[threadIdx.x] = x[(size_t)t * ODIM + threadIdx.x];
    __syncthreads();
    float acc[4] = {0.f, 0.f, 0.f, 0.f};
#pragma unroll 4
    for (int o = 0; o < ODIM; o++) {
        float xv = sx[o];
        const float* pr = g_P + (size_t)o * EMB + threadIdx.x;
#pragma unroll
        for (int c = 0; c < 4; c++) acc[c] += xv * pr[c * 256];
    }
    const float kln = 9.210340371976184f / 1024.0f;   // ln(10000)/EMB
#pragma unroll
    for (int c = 0; c < 4; c++) {
        int e = threadIdx.x + c * 256;
        float freq = expf(-(float)(e & ~1) * kln);
        float arg = (float)s * freq;
        float pe = (e & 1) ? cosf(arg) : sinf(arg);
        g_z[(size_t)t * EMB + e] = acc[c] + pe;
    }
}

// ---------------------------------------------------------------------------
// Attention: 8 warps per block = 8 queries of one (b,h).  grid = B*H*(S/8).
// K/V chunks staged into smem once per block (shared by all warps).
// ---------------------------------------------------------------------------
__global__ void __launch_bounds__(256) attn_kernel(const float* __restrict__ qkv,
                                                   float* __restrict__ out)
{
    const int w = threadIdx.x >> 5, lane = threadIdx.x & 31;
    const int bh = blockIdx.x >> 6;          // / (SEQ/8)
    const int qg = blockIdx.x & 63;
    const int b = bh >> 4, h = bh & 15;
    const int s = qg * 8 + w;

    __shared__ float sq[8][64];
    __shared__ float sp[8][512];
    __shared__ float st[32][68];

    const float* base = qkv + (size_t)(b * SEQ) * E3 + h * (3 * HDIM);
    {
        const float* qp = base + (size_t)s * E3;
        sq[w][lane] = qp[lane];
        sq[w][lane + 32] = qp[lane + 32];
    }

    // --- scores ---
    for (int u0 = 0; u0 < SEQ; u0 += 32) {
        __syncthreads();
#pragma unroll
        for (int i = 0; i < 2; i++) {
            int idx = threadIdx.x + i * 256;        // 0..511
            int r = idx >> 4, c4 = (idx & 15) << 2;
            float4 kk = *(const float4*)(base + (size_t)(u0 + r) * E3 + HDIM + c4);
            *(float4*)(&st[r][c4]) = kk;
        }
        __syncthreads();
        float dot = 0.f;
#pragma unroll
        for (int d = 0; d < 64; d += 4) {
            float4 kk = *(const float4*)(&st[lane][d]);
            dot += kk.x * sq[w][d] + kk.y * sq[w][d + 1]
                 + kk.z * sq[w][d + 2] + kk.w * sq[w][d + 3];
        }
        sp[w][u0 + lane] = dot * 0.125f;
    }
    __syncthreads();

    // --- softmax (per warp over its row of 512) ---
    float mx = -1e30f;
#pragma unroll
    for (int i = 0; i < 16; i++) mx = fmaxf(mx, sp[w][lane + i * 32]);
#pragma unroll
    for (int o = 16; o; o >>= 1) mx = fmaxf(mx, __shfl_xor_sync(0xffffffffu, mx, o));
    float sum = 0.f;
#pragma unroll
    for (int i = 0; i < 16; i++) {
        float p = __expf(sp[w][lane + i * 32] - mx);
        sp[w][lane + i * 32] = p;
        sum += p;
    }
#pragma unroll
    for (int o = 16; o; o >>= 1) sum += __shfl_xor_sync(0xffffffffu, sum, o);
    const float inv = 1.f / sum;

    // --- output: lane owns dims (2*lane, 2*lane+1) ---
    float a0 = 0.f, a1 = 0.f;
    for (int u0 = 0; u0 < SEQ; u0 += 32) {
        __syncthreads();
#pragma unroll
        for (int i = 0; i < 2; i++) {
            int idx = threadIdx.x + i * 256;
            int r = idx >> 4, c4 = (idx & 15) << 2;
            float4 vv = *(const float4*)(base + (size_t)(u0 + r) * E3 + 2 * HDIM + c4);
            *(float4*)(&st[r][c4]) = vv;
        }
        __syncthreads();
#pragma unroll 8
        for (int u = 0; u < 32; u++) {
            float p = sp[w][u0 + u];
            float2 vv = *(const float2*)&st[u][2 * lane];
            a0 += p * vv.x;
            a1 += p * vv.y;
        }
    }
    const int t = b * SEQ + s;
    float* op = out + (size_t)t * EMB + h * HDIM + 2 * lane;
    op[0] = a0 * inv;
    op[1] = a1 * inv;
}

// ---------------------------------------------------------------------------
// Fused residual + LayerNorm (in place on z).  grid(NTOK), 256 threads.
// ---------------------------------------------------------------------------
__device__ __forceinline__ float block_sum256(float v, float* sbuf)
{
#pragma unroll
    for (int o = 16; o; o >>= 1) v += __shfl_xor_sync(0xffffffffu, v, o);
    if ((threadIdx.x & 31) == 0) sbuf[threadIdx.x >> 5] = v;
    __syncthreads();
    float tot = 0.f;
#pragma unroll
    for (int i = 0; i < 8; i++) tot += sbuf[i];
    return tot;
}

__global__ void __launch_bounds__(256) ln_kernel(float* __restrict__ z,
                                                 const float* __restrict__ add,
                                                 const float* __restrict__ g,
                                                 const float* __restrict__ b)
{
    __shared__ float red[16];
    const size_t t = blockIdx.x;
    float* zp = z + t * EMB;
    const float* ap = add + t * EMB;

    float v[4];
    float s = 0.f;
#pragma unroll
    for (int i = 0; i < 4; i++) {
        int e = threadIdx.x + i * 256;
        v[i] = zp[e] + ap[e];
        s += v[i];
    }
    float mean = block_sum256(s, red) * (1.f / 1024.f);
    float q = 0.f;
#pragma unroll
    for (int i = 0; i < 4; i++) { float d = v[i] - mean; q += d * d; }
    float var = block_sum256(q, red + 8) * (1.f / 1024.f);
    float rstd = rsqrtf(var + 1e-5f);
#pragma unroll
    for (int i = 0; i < 4; i++) {
        int e = threadIdx.x + i * 256;
        zp[e] = (v[i] - mean) * rstd * g[e] + b[e];
    }
}

// ---------------------------------------------------------------------------
// Launch
// ---------------------------------------------------------------------------
extern "C" void kernel_launch(void* const* d_in, const int* in_sizes, int n_in,
                              void* d_out, int out_size)
{
    const float* x     = (const float*)d_in[0];
    const float* W_obs = (const float*)d_in[1];
    const float* Wqkv  = (const float*)d_in[2];
    const float* Wo    = (const float*)d_in[3];
    const float* bo    = (const float*)d_in[4];
    const float* ln1g  = (const float*)d_in[5];
    const float* ln1b  = (const float*)d_in[6];
    const float* W1    = (const float*)d_in[7];
    const float* b1    = (const float*)d_in[8];
    const float* W2    = (const float*)d_in[9];
    const float* b2    = (const float*)d_in[10];
    const float* ln2g  = (const float*)d_in[11];
    const float* ln2b  = (const float*)d_in[12];
    float* out = (float*)d_out;

    float *z, *qkvb, *attnb, *tmpb, *hidb, *Mb;
    cudaGetSymbolAddress((void**)&z,     g_z);
    cudaGetSymbolAddress((void**)&qkvb,  g_qkv);
    cudaGetSymbolAddress((void**)&attnb, g_attn);
    cudaGetSymbolAddress((void**)&tmpb,  g_tmp);
    cudaGetSymbolAddress((void**)&hidb,  g_hid);
    cudaGetSymbolAddress((void**)&Mb,    g_M);

    // --- embed: pinv via normal equations ---
    gemm_nt_kernel<<<dim3(1, 1), 256>>>(W_obs, W_obs, nullptr, Mb, ODIM, ODIM, EMB, 0);
    gj_kernel<<<1, 256>>>();
    pmat_kernel<<<dim3(EMB / 256, ODIM), 256>>>(W_obs);
    embed_kernel<<<NTOK, 256>>>(x);

    for (int l = 0; l < NLAYER; l++) {
        const float* wqkv_l = Wqkv + (size_t)l * E3 * EMB;
        const float* wo_l   = Wo   + (size_t)l * EMB * EMB;
        const float* w1_l   = W1   + (size_t)l * HID * EMB;
        const float* w2_l   = W2   + (size_t)l * EMB * HID;

        gemm_nt_kernel<<<dim3(E3 / BN, NTOK / BM), 256>>>(z, wqkv_l, nullptr, qkvb,
                                                          NTOK, E3, EMB, 0);
        attn_kernel<<<BATCH * NHEAD * (SEQ / 8), 256>>>(qkvb, attnb);
        gemm_nt_kernel<<<dim3(EMB / BN, NTOK / BM), 256>>>(attnb, wo_l, bo + l * EMB, tmpb,
                                                           NTOK, EMB, EMB, 1);
        ln_kernel<<<NTOK, 256>>>(z, tmpb, ln1g + l * EMB, ln1b + l * EMB);
        gemm_nt_kernel<<<dim3(HID / BN, NTOK / BM), 256>>>(z, w1_l, b1 + l * HID, hidb,
                                                           NTOK, HID, EMB, 2);
        gemm_nt_kernel<<<dim3(EMB / BN, NTOK / BM), 256>>>(hidb, w2_l, b2 + l * EMB, tmpb,
                                                           NTOK, EMB, HID, 1);
        ln_kernel<<<NTOK, 256>>>(z, tmpb, ln2g + l * EMB, ln2b + l * EMB);
    }

    // --- readout: x_hat = z @ W_obs^T ---
    gemm_nt_kernel<<<dim3(ODIM / BN, NTOK / BM), 256>>>(z, W_obs, nullptr, out,
                                                        NTOK, ODIM, EMB, 0);
}

// round 2
// speedup vs baseline: 1.7153x; 1.7153x over previous
#include <cuda_runtime.h>
#include <cuda_bf16.h>
#include <cstdint>
#include <cstddef>

// Problem constants
#define BATCH 8
#define SEQ   512
#define NTOK  4096      // BATCH*SEQ
#define EMB   1024
#define E3    3072
#define NHEAD 16
#define HDIM  64
#define HID   4096
#define ODIM  128
#define NLAYER 8

// ---------------------------------------------------------------------------
// Scratch (device globals; allocation is forbidden)
// ---------------------------------------------------------------------------
__device__ float g_z   [(size_t)NTOK * EMB];   // 16 MB
__device__ float g_qkv [(size_t)NTOK * E3];    // 48 MB
__device__ float g_attn[(size_t)NTOK * EMB];   // 16 MB
__device__ float g_tmp [(size_t)NTOK * EMB];   // 16 MB
__device__ float g_hid [(size_t)NTOK * HID];   // 64 MB
__device__ float g_M   [ODIM * ODIM];
__device__ float g_aug [ODIM * 2 * ODIM];
__device__ float g_P   [ODIM * EMB];

// ===========================================================================
// Tensor-core GEMM: C[M,N] = A[M,K] * B[N,K]^T using split-bf16 (3 HMMA terms)
// M,N multiples of 128; K multiple of 32.
// ===========================================================================
#define TBM 128
#define TBN 128
#define TBK 32              // k elements per main-loop tile
#define RW  20              // smem words per row: 16 data (32 bf16) + 4 pad
#define PLANE (128 * RW)    // words per plane
#define BUFW  (4 * PLANE)   // 4 planes: A_hi, A_lo, B_hi, B_lo

__device__ __forceinline__ void ldmatrix4(uint32_t addr, uint32_t& r0, uint32_t& r1,
                                          uint32_t& r2, uint32_t& r3)
{
    asm volatile("ldmatrix.sync.aligned.m8n8.x4.shared.b16 {%0,%1,%2,%3}, [%4];"
                 : "=r"(r0), "=r"(r1), "=r"(r2), "=r"(r3) : "r"(addr));
}

__device__ __forceinline__ void mma16816(float* c, uint32_t a0, uint32_t a1,
                                         uint32_t a2, uint32_t a3,
                                         uint32_t b0, uint32_t b1)
{
    asm volatile("mma.sync.aligned.m16n8k16.row.col.f32.bf16.bf16.f32 "
                 "{%0,%1,%2,%3},{%4,%5,%6,%7},{%8,%9},{%0,%1,%2,%3};"
                 : "+f"(c[0]), "+f"(c[1]), "+f"(c[2]), "+f"(c[3])
                 : "r"(a0), "r"(a1), "r"(a2), "r"(a3), "r"(b0), "r"(b1));
}

__device__ __forceinline__ void split2(float x, float y, uint32_t& h, uint32_t& l)
{
    __nv_bfloat162 hv = __floats2bfloat162_rn(x, y);
    float rx = x - __bfloat162float(hv.x);
    float ry = y - __bfloat162float(hv.y);
    __nv_bfloat162 lv = __floats2bfloat162_rn(rx, ry);
    h = *reinterpret_cast<uint32_t*>(&hv);
    l = *reinterpret_cast<uint32_t*>(&lv);
}

__global__ void __launch_bounds__(256, 1) gemm_tc_kernel(
    const float* __restrict__ A, const float* __restrict__ B,
    const float* __restrict__ bias, float* __restrict__ C,
    int M, int N, int K, int op)   // op: 0=none, 1=bias, 2=bias+relu
{
    extern __shared__ uint32_t sm[];
    const uint32_t sbase = (uint32_t)__cvta_generic_to_shared(sm);

    const int tid = threadIdx.x;
    const int lane = tid & 31;
    const int wid = tid >> 5;
    const int wm = wid >> 2;      // 0..1  (64-row slab)
    const int wn = wid & 3;       // 0..3  (32-col slab)
    const int bm = blockIdx.y * TBM;
    const int bn = blockIdx.x * TBN;

    float acc[4][4][4];
#pragma unroll
    for (int i = 0; i < 4; i++)
#pragma unroll
        for (int j = 0; j < 4; j++)
#pragma unroll
            for (int r = 0; r < 4; r++) acc[i][j][r] = 0.f;

    // Global-load mapping: 128 rows x 8 float4 per matrix = 1024 float4 = 4/thread
    int rows[4], c4s[4];
#pragma unroll
    for (int i = 0; i < 4; i++) {
        int f = tid + i * 256;
        rows[i] = f >> 3;
        c4s[i] = (f & 7) << 2;
    }

    const float* Ab = A + (size_t)bm * K;
    const float* Bb = B + (size_t)bn * K;

    float4 ra[4], rb[4];

    // ---- prologue: load + convert + store tile 0 ----
#pragma unroll
    for (int i = 0; i < 4; i++) {
        ra[i] = *(const float4*)(Ab + (size_t)rows[i] * K + c4s[i]);
        rb[i] = *(const float4*)(Bb + (size_t)rows[i] * K + c4s[i]);
    }
    {
        uint32_t* buf = sm;
#pragma unroll
        for (int i = 0; i < 4; i++) {
            uint32_t h0, h1, l0, l1;
            int off = rows[i] * RW + (c4s[i] >> 1);
            split2(ra[i].x, ra[i].y, h0, l0);
            split2(ra[i].z, ra[i].w, h1, l1);
            buf[0 * PLANE + off] = h0; buf[0 * PLANE + off + 1] = h1;
            buf[1 * PLANE + off] = l0; buf[1 * PLANE + off + 1] = l1;
            split2(rb[i].x, rb[i].y, h0, l0);
            split2(rb[i].z, rb[i].w, h1, l1);
            buf[2 * PLANE + off] = h0; buf[2 * PLANE + off + 1] = h1;
            buf[3 * PLANE + off] = l0; buf[3 * PLANE + off + 1] = l1;
        }
    }
    __syncthreads();

    // ldmatrix lane addressing (constant per thread)
    const int arow = wm * 64 + (lane & 7) + ((lane & 8) ? 8 : 0);
    const int akw0 = (lane & 16) ? 4 : 0;
    const int brow = wn * 32 + (lane & 7) + ((lane & 16) ? 8 : 0);
    const int bkw0 = (lane & 8) ? 4 : 0;

    const int T = K / TBK;
    for (int t = 0; t < T; t++) {
        // issue next tile's global loads early
        if (t + 1 < T) {
            const int k0 = (t + 1) * TBK;
#pragma unroll
            for (int i = 0; i < 4; i++) {
                ra[i] = *(const float4*)(Ab + (size_t)rows[i] * K + k0 + c4s[i]);
                rb[i] = *(const float4*)(Bb + (size_t)rows[i] * K + k0 + c4s[i]);
            }
        }

        // ---- compute current tile ----
        const uint32_t bufb = sbase + (uint32_t)((t & 1) * BUFW) * 4u;
#pragma unroll
        for (int ks = 0; ks < 2; ks++) {
            uint32_t ah[4][4], al[4][4], bh[4][2], bl[4][2];
            const int akw = ks * 8 + akw0;
            const int bkw = ks * 8 + bkw0;
#pragma unroll
            for (int mt = 0; mt < 4; mt++) {
                uint32_t ah_addr = bufb + 4u * (0 * PLANE + (arow + mt * 16) * RW + akw);
                ldmatrix4(ah_addr, ah[mt][0], ah[mt][1], ah[mt][2], ah[mt][3]);
                uint32_t al_addr = bufb + 4u * (1 * PLANE + (arow + mt * 16) * RW + akw);
                ldmatrix4(al_addr, al[mt][0], al[mt][1], al[mt][2], al[mt][3]);
            }
#pragma unroll
            for (int np = 0; np < 2; np++) {
                uint32_t r0, r1, r2, r3;
                uint32_t bh_addr = bufb + 4u * (2 * PLANE + (brow + np * 16) * RW + bkw);
                ldmatrix4(bh_addr, r0, r1, r2, r3);
                bh[2 * np][0] = r0; bh[2 * np][1] = r1;
                bh[2 * np + 1][0] = r2; bh[2 * np + 1][1] = r3;
                uint32_t bl_addr = bufb + 4u * (3 * PLANE + (brow + np * 16) * RW + bkw);
                ldmatrix4(bl_addr, r0, r1, r2, r3);
                bl[2 * np][0] = r0; bl[2 * np][1] = r1;
                bl[2 * np + 1][0] = r2; bl[2 * np + 1][1] = r3;
            }
#pragma unroll
            for (int mt = 0; mt < 4; mt++)
#pragma unroll
                for (int nt = 0; nt < 4; nt++) {
                    float* c = acc[mt][nt];
                    mma16816(c, ah[mt][0], ah[mt][1], ah[mt][2], ah[mt][3],
                             bh[nt][0], bh[nt][1]);
                    mma16816(c, ah[mt][0], ah[mt][1], ah[mt][2], ah[mt][3],
                             bl[nt][0], bl[nt][1]);
                    mma16816(c, al[mt][0], al[mt][1], al[mt][2], al[mt][3],
                             bh[nt][0], bh[nt][1]);
                }
        }

        // ---- convert + store next tile into the other buffer ----
        if (t + 1 < T) {
            uint32_t* buf = sm + ((t + 1) & 1) * BUFW;
#pragma unroll
            for (int i = 0; i < 4; i++) {
                uint32_t h0, h1, l0, l1;
                int off = rows[i] * RW + (c4s[i] >> 1);
                split2(ra[i].x, ra[i].y, h0, l0);
                split2(ra[i].z, ra[i].w, h1, l1);
                buf[0 * PLANE + off] = h0; buf[0 * PLANE + off + 1] = h1;
                buf[1 * PLANE + off] = l0; buf[1 * PLANE + off + 1] = l1;
                split2(rb[i].x, rb[i].y, h0, l0);
                split2(rb[i].z, rb[i].w, h1, l1);
                buf[2 * PLANE + off] = h0; buf[2 * PLANE + off + 1] = h1;
                buf[3 * PLANE + off] = l0; buf[3 * PLANE + off + 1] = l1;
            }
        }
        __syncthreads();
    }

    // ---- epilogue ----
#pragma unroll
    for (int mt = 0; mt < 4; mt++) {
        const int row = bm + wm * 64 + mt * 16 + (lane >> 2);
#pragma unroll
        for (int nt = 0; nt < 4; nt++) {
            const int col = bn + wn * 32 + nt * 8 + 2 * (lane & 3);
            float b0 = 0.f, b1 = 0.f;
            if (op >= 1) { b0 = bias[col]; b1 = bias[col + 1]; }
            float v0 = acc[mt][nt][0] + b0;
            float v1 = acc[mt][nt][1] + b1;
            float v2 = acc[mt][nt][2] + b0;
            float v3 = acc[mt][nt][3] + b1;
            if (op == 2) {
                v0 = fmaxf(v0, 0.f); v1 = fmaxf(v1, 0.f);
                v2 = fmaxf(v2, 0.f); v3 = fmaxf(v3, 0.f);
            }
            float2 p01 = make_float2(v0, v1);
            float2 p23 = make_float2(v2, v3);
            *(float2*)(C + (size_t)row * N + col) = p01;
            *(float2*)(C + (size_t)(row + 8) * N + col) = p23;
        }
    }
}

// ---------------------------------------------------------------------------
// fp32 fallback GEMM (used only for the 128x128 normal-equations matrix)
// ---------------------------------------------------------------------------
#define BM 128
#define BN 128
#define BK 32

__global__ void __launch_bounds__(256) gemm_f32_kernel(
    const float* __restrict__ A, const float* __restrict__ B,
    const float* __restrict__ bias, float* __restrict__ C,
    int M, int N, int K, int op)
{
    __shared__ float As[BK][BM + 4];
    __shared__ float Bs[BK][BN + 4];

    const int bm = blockIdx.y * BM;
    const int bn = blockIdx.x * BN;
    const int tid = threadIdx.x;
    const int tm = (tid >> 4) << 3;
    const int tn = (tid & 15) << 3;

    float acc[8][8];
#pragma unroll
    for (int i = 0; i < 8; i++)
#pragma unroll
        for (int j = 0; j < 8; j++) acc[i][j] = 0.f;

    for (int k0 = 0; k0 < K; k0 += BK) {
#pragma unroll
        for (int i = 0; i < 4; i++) {
            int idx = tid + i * 256;
            int row = idx >> 3;
            int col = (idx & 7) << 2;
            float4 a = *(const float4*)(A + (size_t)(bm + row) * K + k0 + col);
            As[col + 0][row] = a.x; As[col + 1][row] = a.y;
            As[col + 2][row] = a.z; As[col + 3][row] = a.w;
            float4 b = *(const float4*)(B + (size_t)(bn + row) * K + k0 + col);
            Bs[col + 0][row] = b.x; Bs[col + 1][row] = b.y;
            Bs[col + 2][row] = b.z; Bs[col + 3][row] = b.w;
        }
        __syncthreads();
#pragma unroll
        for (int kk = 0; kk < BK; kk++) {
            float4 a0 = *(const float4*)&As[kk][tm];
            float4 a1 = *(const float4*)&As[kk][tm + 4];
            float4 b0 = *(const float4*)&Bs[kk][tn];
            float4 b1 = *(const float4*)&Bs[kk][tn + 4];
            float av[8] = {a0.x, a0.y, a0.z, a0.w, a1.x, a1.y, a1.z, a1.w};
            float bv[8] = {b0.x, b0.y, b0.z, b0.w, b1.x, b1.y, b1.z, b1.w};
#pragma unroll
            for (int i = 0; i < 8; i++)
#pragma unroll
                for (int j = 0; j < 8; j++)
                    acc[i][j] += av[i] * bv[j];
        }
        __syncthreads();
    }

#pragma unroll
    for (int i = 0; i < 8; i++) {
        size_t m = bm + tm + i;
#pragma unroll
        for (int j = 0; j < 8; j++) {
            int n = bn + tn + j;
            float v = acc[i][j];
            if (op >= 1) v += bias[n];
            if (op == 2) v = fmaxf(v, 0.f);
            C[m * N + n] = v;
        }
    }
}

// ---------------------------------------------------------------------------
// Gauss-Jordan inverse of SPD 128x128 g_M -> right half of g_aug
// ---------------------------------------------------------------------------
__global__ void __launch_bounds__(256) gj_kernel()
{
    const int tid = threadIdx.x;
    for (int idx = tid; idx < ODIM * 2 * ODIM; idx += 256) {
        int r = idx >> 8, c = idx & 255;
        g_aug[idx] = (c < ODIM) ? g_M[r * ODIM + c] : ((c - ODIM) == r ? 1.f : 0.f);
    }
    __syncthreads();

    const int r = tid >> 1;
    const int cb = (tid & 1) << 7;
    for (int k = 0; k < ODIM; k++) {
        float ip = 1.f / g_aug[k * 256 + k];
        __syncthreads();
        g_aug[k * 256 + tid] *= ip;
        __syncthreads();
        float f = (r != k) ? g_aug[r * 256 + k] : 0.f;
        __syncthreads();
        const float* prow = &g_aug[k * 256 + cb];
        float* rrow = &g_aug[r * 256 + cb];
#pragma unroll 8
        for (int c = 0; c < 128; c++) rrow[c] -= f * prow[c];
        __syncthreads();
    }
}

// P[o][e] = sum_j Minv[o][j] * W_obs[j][e]
__global__ void __launch_bounds__(256) pmat_kernel(const float* __restrict__ W)
{
    const int o = blockIdx.y;
    const int e = blockIdx.x * 256 + threadIdx.x;
    __shared__ float smv[ODIM];
    if (threadIdx.x < ODIM) smv[threadIdx.x] = g_aug[o * 256 + ODIM + threadIdx.x];
    __syncthreads();
    float acc = 0.f;
#pragma unroll 8
    for (int j = 0; j < ODIM; j++) acc += smv[j] * W[(size_t)j * EMB + e];
    g_P[(size_t)o * EMB + e] = acc;
}

// z[t][e] = sum_o x[t][o] * P[o][e] + PE(s,e)
__global__ void __launch_bounds__(256) embed_kernel(const float* __restrict__ x)
{
    const int t = blockIdx.x;
    const int s = t & (SEQ - 1);
    __shared__ float sx[ODIM];
    if (threadIdx.x < ODIM) sx[threadIdx.x] = x[(size_t)t * ODIM + threadIdx.x];
    __syncthreads();
    float acc[4] = {0.f, 0.f, 0.f, 0.f};
#pragma unroll 4
    for (int o = 0; o < ODIM; o++) {
        float xv = sx[o];
        const float* pr = g_P + (size_t)o * EMB + threadIdx.x;
#pragma unroll
        for (int c = 0; c < 4; c++) acc[c] += xv * pr[c * 256];
    }
    const float kln = 9.210340371976184f / 1024.0f;
#pragma unroll
    for (int c = 0; c < 4; c++) {
        int e = threadIdx.x + c * 256;
        float freq = expf(-(float)(e & ~1) * kln);
        float arg = (float)s * freq;
        float pe = (e & 1) ? cosf(arg) : sinf(arg);
        g_z[(size_t)t * EMB + e] = acc[c] + pe;
    }
}

// ---------------------------------------------------------------------------
// Attention: 8 warps per block = 8 queries of one (b,h)
// ---------------------------------------------------------------------------
__global__ void __launch_bounds__(256) attn_kernel(const float* __restrict__ qkv,
                                                   float* __restrict__ out)
{
    const int w = threadIdx.x >> 5, lane = threadIdx.x & 31;
    const int bh = blockIdx.x >> 6;
    const int qg = blockIdx.x & 63;
    const int b = bh >> 4, h = bh & 15;
    const int s = qg * 8 + w;

    __shared__ float sq[8][64];
    __shared__ float sp[8][512];
    __shared__ float st[32][68];

    const float* base = qkv + (size_t)(b * SEQ) * E3 + h * (3 * HDIM);
    {
        const float* qp = base + (size_t)s * E3;
        sq[w][lane] = qp[lane];
        sq[w][lane + 32] = qp[lane + 32];
    }

    for (int u0 = 0; u0 < SEQ; u0 += 32) {
        __syncthreads();
#pragma unroll
        for (int i = 0; i < 2; i++) {
            int idx = threadIdx.x + i * 256;
            int r = idx >> 4, c4 = (idx & 15) << 2;
            float4 kk = *(const float4*)(base + (size_t)(u0 + r) * E3 + HDIM + c4);
            *(float4*)(&st[r][c4]) = kk;
        }
        __syncthreads();
        float dot = 0.f;
#pragma unroll
        for (int d = 0; d < 64; d += 4) {
            float4 kk = *(const float4*)(&st[lane][d]);
            dot += kk.x * sq[w][d] + kk.y * sq[w][d + 1]
                 + kk.z * sq[w][d + 2] + kk.w * sq[w][d + 3];
        }
        sp[w][u0 + lane] = dot * 0.125f;
    }
    __syncthreads();

    float mx = -1e30f;
#pragma unroll
    for (int i = 0; i < 16; i++) mx = fmaxf(mx, sp[w][lane + i * 32]);
#pragma unroll
    for (int o = 16; o; o >>= 1) mx = fmaxf(mx, __shfl_xor_sync(0xffffffffu, mx, o));
    float sum = 0.f;
#pragma unroll
    for (int i = 0; i < 16; i++) {
        float p = __expf(sp[w][lane + i * 32] - mx);
        sp[w][lane + i * 32] = p;
        sum += p;
    }
#pragma unroll
    for (int o = 16; o; o >>= 1) sum += __shfl_xor_sync(0xffffffffu, sum, o);
    const float inv = 1.f / sum;

    float a0 = 0.f, a1 = 0.f;
    for (int u0 = 0; u0 < SEQ; u0 += 32) {
        __syncthreads();
#pragma unroll
        for (int i = 0; i < 2; i++) {
            int idx = threadIdx.x + i * 256;
            int r = idx >> 4, c4 = (idx & 15) << 2;
            float4 vv = *(const float4*)(base + (size_t)(u0 + r) * E3 + 2 * HDIM + c4);
            *(float4*)(&st[r][c4]) = vv;
        }
        __syncthreads();
#pragma unroll 8
        for (int u = 0; u < 32; u++) {
            float p = sp[w][u0 + u];
            float2 vv = *(const float2*)&st[u][2 * lane];
            a0 += p * vv.x;
            a1 += p * vv.y;
        }
    }
    const int t = b * SEQ + s;
    float* op = out + (size_t)t * EMB + h * HDIM + 2 * lane;
    op[0] = a0 * inv;
    op[1] = a1 * inv;
}

// ---------------------------------------------------------------------------
// Fused residual + LayerNorm
// ---------------------------------------------------------------------------
__device__ __forceinline__ float block_sum256(float v, float* sbuf)
{
#pragma unroll
    for (int o = 16; o; o >>= 1) v += __shfl_xor_sync(0xffffffffu, v, o);
    if ((threadIdx.x & 31) == 0) sbuf[threadIdx.x >> 5] = v;
    __syncthreads();
    float tot = 0.f;
#pragma unroll
    for (int i = 0; i < 8; i++) tot += sbuf[i];
    return tot;
}

__global__ void __launch_bounds__(256) ln_kernel(float* __restrict__ z,
                                                 const float* __restrict__ add,
                                                 const float* __restrict__ g,
                                                 const float* __restrict__ b)
{
    __shared__ float red[16];
    const size_t t = blockIdx.x;
    float* zp = z + t * EMB;
    const float* ap = add + t * EMB;

    float v[4];
    float s = 0.f;
#pragma unroll
    for (int i = 0; i < 4; i++) {
        int e = threadIdx.x + i * 256;
        v[i] = zp[e] + ap[e];
        s += v[i];
    }
    float mean = block_sum256(s, red) * (1.f / 1024.f);
    float q = 0.f;
#pragma unroll
    for (int i = 0; i < 4; i++) { float d = v[i] - mean; q += d * d; }
    float var = block_sum256(q, red + 8) * (1.f / 1024.f);
    float rstd = rsqrtf(var + 1e-5f);
#pragma unroll
    for (int i = 0; i < 4; i++) {
        int e = threadIdx.x + i * 256;
        zp[e] = (v[i] - mean) * rstd * g[e] + b[e];
    }
}

// ---------------------------------------------------------------------------
// Launch
// ---------------------------------------------------------------------------
#define TC_SMEM (2 * BUFW * 4)

extern "C" void kernel_launch(void* const* d_in, const int* in_sizes, int n_in,
                              void* d_out, int out_size)
{
    const float* x     = (const float*)d_in[0];
    const float* W_obs = (const float*)d_in[1];
    const float* Wqkv  = (const float*)d_in[2];
    const float* Wo    = (const float*)d_in[3];
    const float* bo    = (const float*)d_in[4];
    const float* ln1g  = (const float*)d_in[5];
    const float* ln1b  = (const float*)d_in[6];
    const float* W1    = (const float*)d_in[7];
    const float* b1    = (const float*)d_in[8];
    const float* W2    = (const float*)d_in[9];
    const float* b2    = (const float*)d_in[10];
    const float* ln2g  = (const float*)d_in[11];
    const float* ln2b  = (const float*)d_in[12];
    float* out = (float*)d_out;

    float *z, *qkvb, *attnb, *tmpb, *hidb, *Mb;
    cudaGetSymbolAddress((void**)&z,     g_z);
    cudaGetSymbolAddress((void**)&qkvb,  g_qkv);
    cudaGetSymbolAddress((void**)&attnb, g_attn);
    cudaGetSymbolAddress((void**)&tmpb,  g_tmp);
    cudaGetSymbolAddress((void**)&hidb,  g_hid);
    cudaGetSymbolAddress((void**)&Mb,    g_M);

    cudaFuncSetAttribute(gemm_tc_kernel,
                         cudaFuncAttributeMaxDynamicSharedMemorySize, TC_SMEM);

    // --- embed: pinv via normal equations (kept fp32 for conditioning) ---
    gemm_f32_kernel<<<dim3(1, 1), 256>>>(W_obs, W_obs, nullptr, Mb, ODIM, ODIM, EMB, 0);
    gj_kernel<<<1, 256>>>();
    pmat_kernel<<<dim3(EMB / 256, ODIM), 256>>>(W_obs);
    embed_kernel<<<NTOK, 256>>>(x);

    for (int l = 0; l < NLAYER; l++) {
        const float* wqkv_l = Wqkv + (size_t)l * E3 * EMB;
        const float* wo_l   = Wo   + (size_t)l * EMB * EMB;
        const float* w1_l   = W1   + (size_t)l * HID * EMB;
        const float* w2_l   = W2   + (size_t)l * EMB * HID;

        gemm_tc_kernel<<<dim3(E3 / TBN, NTOK / TBM), 256, TC_SMEM>>>(
            z, wqkv_l, nullptr, qkvb, NTOK, E3, EMB, 0);
        attn_kernel<<<BATCH * NHEAD * (SEQ / 8), 256>>>(qkvb, attnb);
        gemm_tc_kernel<<<dim3(EMB / TBN, NTOK / TBM), 256, TC_SMEM>>>(
            attnb, wo_l, bo + l * EMB, tmpb, NTOK, EMB, EMB, 1);
        ln_kernel<<<NTOK, 256>>>(z, tmpb, ln1g + l * EMB, ln1b + l * EMB);
        gemm_tc_kernel<<<dim3(HID / TBN, NTOK / TBM), 256, TC_SMEM>>>(
            z, w1_l, b1 + l * HID, hidb, NTOK, HID, EMB, 2);
        gemm_tc_kernel<<<dim3(EMB / TBN, NTOK / TBM), 256, TC_SMEM>>>(
            hidb, w2_l, b2 + l * EMB, tmpb, NTOK, EMB, HID, 1);
        ln_kernel<<<NTOK, 256>>>(z, tmpb, ln2g + l * EMB, ln2b + l * EMB);
    }

    // --- readout: x_hat = z @ W_obs^T ---
    gemm_tc_kernel<<<dim3(ODIM / TBN, NTOK / TBM), 256, TC_SMEM>>>(
        z, W_obs, nullptr, out, NTOK, ODIM, EMB, 0);
}